// round 1
// baseline (speedup 1.0000x reference)
#include <cuda_runtime.h>

#ifndef B_DIM
#define B_DIM 8
#define N_DIM 8192
#define M_DIM 128
#endif

constexpr int WARPS_PER_CTA = 8;
constexpr int PTS_PER_WARP  = 8;
constexpr int PTS_PER_CTA   = WARPS_PER_CTA * PTS_PER_WARP;  // 64
constexpr int THREADS       = WARPS_PER_CTA * 32;            // 256

__device__ __forceinline__ float leaky(float x) {
    // x>=0 -> x >= 0.2x ; x<0 -> x < 0.2x  => max(x, 0.2x) == leaky_relu(x, 0.2)
    return fmaxf(x, 0.2f * x);
}

__global__ void __launch_bounds__(THREADS)
featuration_kernel(const float* __restrict__ xyz,   // [B,3,N]
                   const float* __restrict__ V,     // [B,M,3]
                   const float* __restrict__ W1,    // [4,4]
                   const float* __restrict__ b1,    // [4]
                   const float* __restrict__ W2,    // [4,4]
                   const float* __restrict__ b2,    // [4]
                   const float* __restrict__ W3,    // [1,4]
                   const float* __restrict__ b3,    // [1]
                   float* __restrict__ out)         // [B,N,M]
{
    __shared__ float4 Vs[M_DIM];   // (Vx,Vy,Vz,0) per m
    __shared__ float4 Cs[M_DIM];   // hoisted layer-1 constants per m

    const int b   = blockIdx.y;
    const int tid = threadIdx.x;

    // ---- per-CTA init: load V for this batch, precompute layer-1 constants ----
    if (tid < M_DIM) {
        const float vx = __ldg(&V[(b * M_DIM + tid) * 3 + 0]);
        const float vy = __ldg(&V[(b * M_DIM + tid) * 3 + 1]);
        const float vz = __ldg(&V[(b * M_DIM + tid) * 3 + 2]);
        Vs[tid] = make_float4(vx, vy, vz, 0.0f);
        float4 c;
        c.x = fmaf(__ldg(&W1[1]),  vx, fmaf(__ldg(&W1[2]),  vy, fmaf(__ldg(&W1[3]),  vz, __ldg(&b1[0]))));
        c.y = fmaf(__ldg(&W1[5]),  vx, fmaf(__ldg(&W1[6]),  vy, fmaf(__ldg(&W1[7]),  vz, __ldg(&b1[1]))));
        c.z = fmaf(__ldg(&W1[9]),  vx, fmaf(__ldg(&W1[10]), vy, fmaf(__ldg(&W1[11]), vz, __ldg(&b1[2]))));
        c.w = fmaf(__ldg(&W1[13]), vx, fmaf(__ldg(&W1[14]), vy, fmaf(__ldg(&W1[15]), vz, __ldg(&b1[3]))));
        Cs[tid] = c;
    }

    // ---- weights into registers (L1-broadcast loads, tiny) ----
    const float a0 = __ldg(&W1[0]),  a1 = __ldg(&W1[4]),
                a2 = __ldg(&W1[8]),  a3 = __ldg(&W1[12]);
    float w2[16];
#pragma unroll
    for (int i = 0; i < 16; i++) w2[i] = __ldg(&W2[i]);
    const float bb2_0 = __ldg(&b2[0]), bb2_1 = __ldg(&b2[1]),
                bb2_2 = __ldg(&b2[2]), bb2_3 = __ldg(&b2[3]);
    const float w3_0 = __ldg(&W3[0]), w3_1 = __ldg(&W3[1]),
                w3_2 = __ldg(&W3[2]), w3_3 = __ldg(&W3[3]);
    const float bb3 = __ldg(&b3[0]);

    __syncthreads();

    const int warp = tid >> 5;
    const int lane = tid & 31;

    // lane owns m = 4*lane .. 4*lane+3
    const float4 v0 = Vs[4 * lane + 0];
    const float4 v1 = Vs[4 * lane + 1];
    const float4 v2 = Vs[4 * lane + 2];
    const float4 v3 = Vs[4 * lane + 3];
    const float4 c0 = Cs[4 * lane + 0];
    const float4 c1 = Cs[4 * lane + 1];
    const float4 c2 = Cs[4 * lane + 2];
    const float4 c3 = Cs[4 * lane + 3];

    const float* xb = xyz + (size_t)b * 3 * N_DIM;
    float* outb = out + (size_t)b * N_DIM * M_DIM;

    const int n_base = blockIdx.x * PTS_PER_CTA + warp * PTS_PER_WARP;

#pragma unroll
    for (int p = 0; p < PTS_PER_WARP; p++) {
        const int n = n_base + p;
        // broadcast loads (all lanes same address)
        const float px = __ldg(&xb[n]);
        const float py = __ldg(&xb[N_DIM + n]);
        const float pz = __ldg(&xb[2 * N_DIM + n]);

        float dx, dy, dz, s;
        dx = px - v0.x; dy = py - v0.y; dz = pz - v0.z;
        s = fmaf(dx, dx, fmaf(dy, dy, dz * dz));
        const float d0 = sqrtf(s);
        dx = px - v1.x; dy = py - v1.y; dz = pz - v1.z;
        s = fmaf(dx, dx, fmaf(dy, dy, dz * dz));
        const float d1 = sqrtf(s);
        dx = px - v2.x; dy = py - v2.y; dz = pz - v2.z;
        s = fmaf(dx, dx, fmaf(dy, dy, dz * dz));
        const float d2 = sqrtf(s);
        dx = px - v3.x; dy = py - v3.y; dz = pz - v3.z;
        s = fmaf(dx, dx, fmaf(dy, dy, dz * dz));
        const float d3 = sqrtf(s);

        // warp-wide min/max over all 128 m
        float mn = fminf(fminf(d0, d1), fminf(d2, d3));
        float mx = fmaxf(fmaxf(d0, d1), fmaxf(d2, d3));
#pragma unroll
        for (int off = 16; off > 0; off >>= 1) {
            mn = fminf(mn, __shfl_xor_sync(0xFFFFFFFFu, mn, off));
            mx = fmaxf(mx, __shfl_xor_sync(0xFFFFFFFFu, mx, off));
        }
        const float denom = mx - mn;
        const float inv = (denom > 0.0f) ? (1.0f / denom) : 0.0f;  // f=0 when denom==0

        float4 res;
        {
            // element 0
            const float f = (d0 - mn) * inv;
            const float h0 = leaky(fmaf(a0, f, c0.x));
            const float h1 = leaky(fmaf(a1, f, c0.y));
            const float h2 = leaky(fmaf(a2, f, c0.z));
            const float h3 = leaky(fmaf(a3, f, c0.w));
            const float g0 = leaky(fmaf(w2[0],  h0, fmaf(w2[1],  h1, fmaf(w2[2],  h2, fmaf(w2[3],  h3, bb2_0)))));
            const float g1 = leaky(fmaf(w2[4],  h0, fmaf(w2[5],  h1, fmaf(w2[6],  h2, fmaf(w2[7],  h3, bb2_1)))));
            const float g2 = leaky(fmaf(w2[8],  h0, fmaf(w2[9],  h1, fmaf(w2[10], h2, fmaf(w2[11], h3, bb2_2)))));
            const float g3 = leaky(fmaf(w2[12], h0, fmaf(w2[13], h1, fmaf(w2[14], h2, fmaf(w2[15], h3, bb2_3)))));
            res.x = fmaf(w3_0, g0, fmaf(w3_1, g1, fmaf(w3_2, g2, fmaf(w3_3, g3, bb3))));
        }
        {
            const float f = (d1 - mn) * inv;
            const float h0 = leaky(fmaf(a0, f, c1.x));
            const float h1 = leaky(fmaf(a1, f, c1.y));
            const float h2 = leaky(fmaf(a2, f, c1.z));
            const float h3 = leaky(fmaf(a3, f, c1.w));
            const float g0 = leaky(fmaf(w2[0],  h0, fmaf(w2[1],  h1, fmaf(w2[2],  h2, fmaf(w2[3],  h3, bb2_0)))));
            const float g1 = leaky(fmaf(w2[4],  h0, fmaf(w2[5],  h1, fmaf(w2[6],  h2, fmaf(w2[7],  h3, bb2_1)))));
            const float g2 = leaky(fmaf(w2[8],  h0, fmaf(w2[9],  h1, fmaf(w2[10], h2, fmaf(w2[11], h3, bb2_2)))));
            const float g3 = leaky(fmaf(w2[12], h0, fmaf(w2[13], h1, fmaf(w2[14], h2, fmaf(w2[15], h3, bb2_3)))));
            res.y = fmaf(w3_0, g0, fmaf(w3_1, g1, fmaf(w3_2, g2, fmaf(w3_3, g3, bb3))));
        }
        {
            const float f = (d2 - mn) * inv;
            const float h0 = leaky(fmaf(a0, f, c2.x));
            const float h1 = leaky(fmaf(a1, f, c2.y));
            const float h2 = leaky(fmaf(a2, f, c2.z));
            const float h3 = leaky(fmaf(a3, f, c2.w));
            const float g0 = leaky(fmaf(w2[0],  h0, fmaf(w2[1],  h1, fmaf(w2[2],  h2, fmaf(w2[3],  h3, bb2_0)))));
            const float g1 = leaky(fmaf(w2[4],  h0, fmaf(w2[5],  h1, fmaf(w2[6],  h2, fmaf(w2[7],  h3, bb2_1)))));
            const float g2 = leaky(fmaf(w2[8],  h0, fmaf(w2[9],  h1, fmaf(w2[10], h2, fmaf(w2[11], h3, bb2_2)))));
            const float g3 = leaky(fmaf(w2[12], h0, fmaf(w2[13], h1, fmaf(w2[14], h2, fmaf(w2[15], h3, bb2_3)))));
            res.z = fmaf(w3_0, g0, fmaf(w3_1, g1, fmaf(w3_2, g2, fmaf(w3_3, g3, bb3))));
        }
        {
            const float f = (d3 - mn) * inv;
            const float h0 = leaky(fmaf(a0, f, c3.x));
            const float h1 = leaky(fmaf(a1, f, c3.y));
            const float h2 = leaky(fmaf(a2, f, c3.z));
            const float h3 = leaky(fmaf(a3, f, c3.w));
            const float g0 = leaky(fmaf(w2[0],  h0, fmaf(w2[1],  h1, fmaf(w2[2],  h2, fmaf(w2[3],  h3, bb2_0)))));
            const float g1 = leaky(fmaf(w2[4],  h0, fmaf(w2[5],  h1, fmaf(w2[6],  h2, fmaf(w2[7],  h3, bb2_1)))));
            const float g2 = leaky(fmaf(w2[8],  h0, fmaf(w2[9],  h1, fmaf(w2[10], h2, fmaf(w2[11], h3, bb2_2)))));
            const float g3 = leaky(fmaf(w2[12], h0, fmaf(w2[13], h1, fmaf(w2[14], h2, fmaf(w2[15], h3, bb2_3)))));
            res.w = fmaf(w3_0, g0, fmaf(w3_1, g1, fmaf(w3_2, g2, fmaf(w3_3, g3, bb3))));
        }

        // coalesced: warp writes 128 contiguous floats
        reinterpret_cast<float4*>(outb + (size_t)n * M_DIM)[lane] = res;
    }
}

extern "C" void kernel_launch(void* const* d_in, const int* in_sizes, int n_in,
                              void* d_out, int out_size) {
    const float* xyz = (const float*)d_in[0];
    const float* V   = (const float*)d_in[1];
    const float* W1  = (const float*)d_in[2];
    const float* b1  = (const float*)d_in[3];
    const float* W2  = (const float*)d_in[4];
    const float* b2  = (const float*)d_in[5];
    const float* W3  = (const float*)d_in[6];
    const float* b3  = (const float*)d_in[7];
    float* out = (float*)d_out;

    dim3 grid(N_DIM / PTS_PER_CTA, B_DIM);  // (128, 8)
    featuration_kernel<<<grid, THREADS>>>(xyz, V, W1, b1, W2, b2, W3, b3, out);
}

// round 3
// speedup vs baseline: 1.1848x; 1.1848x over previous
#include <cuda_runtime.h>

#ifndef B_DIM
#define B_DIM 8
#define N_DIM 8192
#define M_DIM 128
#endif

constexpr int WARPS_PER_CTA = 8;
constexpr int PTS_PER_WARP  = 8;
constexpr int PTS_PER_CTA   = WARPS_PER_CTA * PTS_PER_WARP;  // 64
constexpr int THREADS       = WARPS_PER_CTA * 32;            // 256

typedef unsigned long long u64;

// ---------- packed f32x2 helpers (Blackwell) ----------
__device__ __forceinline__ u64 pack2(float lo, float hi) {
    u64 r; asm("mov.b64 %0, {%1,%2};" : "=l"(r) : "f"(lo), "f"(hi)); return r;
}
__device__ __forceinline__ void unpack2(u64 v, float& lo, float& hi) {
    asm("mov.b64 {%0,%1}, %2;" : "=f"(lo), "=f"(hi) : "l"(v));
}
__device__ __forceinline__ u64 fma2(u64 a, u64 b, u64 c) {
    u64 d; asm("fma.rn.f32x2 %0, %1, %2, %3;" : "=l"(d) : "l"(a), "l"(b), "l"(c)); return d;
}
__device__ __forceinline__ u64 mul2(u64 a, u64 b) {
    u64 d; asm("mul.rn.f32x2 %0, %1, %2;" : "=l"(d) : "l"(a), "l"(b)); return d;
}
__device__ __forceinline__ u64 add2(u64 a, u64 b) {
    u64 d; asm("add.rn.f32x2 %0, %1, %2;" : "=l"(d) : "l"(a), "l"(b)); return d;
}

__device__ __forceinline__ float sqrt_approx(float x) {
    float r; asm("sqrt.approx.f32 %0, %1;" : "=f"(r) : "f"(x)); return r;
}
__device__ __forceinline__ float rcp_approx(float x) {
    float r; asm("rcp.approx.f32 %0, %1;" : "=f"(r) : "f"(x)); return r;
}

// packed leaky: max(z, 0.2z) per component
__device__ __forceinline__ u64 leaky2(u64 z, u64 k02) {
    u64 t = mul2(z, k02);
    float z0, z1, t0, t1;
    unpack2(z, z0, z1); unpack2(t, t0, t1);
    return pack2(fmaxf(z0, t0), fmaxf(z1, t1));
}

struct MlpConsts {
    u64 a01, a23;              // layer-1 f-coeffs packed across hidden pairs
    u64 w2p01[4], w2p23[4];    // w2p01[i] = (W2[0][i], W2[1][i]); w2p23[i] = (W2[2][i], W2[3][i])
    u64 b2p01, b2p23;
    u64 w3p01, w3p23;
    u64 b3p;                   // (b3, 0)
    u64 k02;                   // (0.2, 0.2)
};

// full MLP for one element given f and its per-m layer-1 constants (packed across hidden dim)
__device__ __forceinline__ float mlp_eval(float f, u64 c01, u64 c23, const MlpConsts& C) {
    const u64 fs = pack2(f, f);
    const u64 h01 = leaky2(fma2(C.a01, fs, c01), C.k02);
    const u64 h23 = leaky2(fma2(C.a23, fs, c23), C.k02);
    float h0, h1, h2, h3;
    unpack2(h01, h0, h1); unpack2(h23, h2, h3);
    const u64 h0s = pack2(h0, h0), h1s = pack2(h1, h1),
              h2s = pack2(h2, h2), h3s = pack2(h3, h3);
    u64 z2a = fma2(h0s, C.w2p01[0],
              fma2(h1s, C.w2p01[1],
              fma2(h2s, C.w2p01[2],
              fma2(h3s, C.w2p01[3], C.b2p01))));
    u64 z2b = fma2(h0s, C.w2p23[0],
              fma2(h1s, C.w2p23[1],
              fma2(h2s, C.w2p23[2],
              fma2(h3s, C.w2p23[3], C.b2p23))));
    const u64 g01 = leaky2(z2a, C.k02);
    const u64 g23 = leaky2(z2b, C.k02);
    const u64 acc = fma2(C.w3p01, g01, fma2(C.w3p23, g23, C.b3p));
    float lo, hi; unpack2(acc, lo, hi);
    return lo + hi;
}

__global__ void __launch_bounds__(THREADS)
featuration_kernel(const float* __restrict__ xyz,   // [B,3,N]
                   const float* __restrict__ V,     // [B,M,3]
                   const float* __restrict__ W1,    // [4,4]
                   const float* __restrict__ b1,    // [4]
                   const float* __restrict__ W2,    // [4,4]
                   const float* __restrict__ b2,    // [4]
                   const float* __restrict__ W3,    // [1,4]
                   const float* __restrict__ b3,    // [1]
                   float* __restrict__ out)         // [B,N,M]
{
    __shared__ float4 Vs[M_DIM];   // (Vx,Vy,Vz,0) per m
    __shared__ float4 Cs[M_DIM];   // hoisted layer-1 constants per m

    const int b   = blockIdx.y;
    const int tid = threadIdx.x;

    // ---- per-CTA init: load V for this batch, precompute layer-1 constants ----
    if (tid < M_DIM) {
        const float vx = __ldg(&V[(b * M_DIM + tid) * 3 + 0]);
        const float vy = __ldg(&V[(b * M_DIM + tid) * 3 + 1]);
        const float vz = __ldg(&V[(b * M_DIM + tid) * 3 + 2]);
        Vs[tid] = make_float4(vx, vy, vz, 0.0f);
        float4 c;
        c.x = fmaf(__ldg(&W1[1]),  vx, fmaf(__ldg(&W1[2]),  vy, fmaf(__ldg(&W1[3]),  vz, __ldg(&b1[0]))));
        c.y = fmaf(__ldg(&W1[5]),  vx, fmaf(__ldg(&W1[6]),  vy, fmaf(__ldg(&W1[7]),  vz, __ldg(&b1[1]))));
        c.z = fmaf(__ldg(&W1[9]),  vx, fmaf(__ldg(&W1[10]), vy, fmaf(__ldg(&W1[11]), vz, __ldg(&b1[2]))));
        c.w = fmaf(__ldg(&W1[13]), vx, fmaf(__ldg(&W1[14]), vy, fmaf(__ldg(&W1[15]), vz, __ldg(&b1[3]))));
        Cs[tid] = c;
    }

    // ---- global weight constants, packed across the hidden axis ----
    MlpConsts C;
    C.a01 = pack2(__ldg(&W1[0]),  __ldg(&W1[4]));
    C.a23 = pack2(__ldg(&W1[8]),  __ldg(&W1[12]));
#pragma unroll
    for (int i = 0; i < 4; i++) {
        C.w2p01[i] = pack2(__ldg(&W2[i]),     __ldg(&W2[4 + i]));
        C.w2p23[i] = pack2(__ldg(&W2[8 + i]), __ldg(&W2[12 + i]));
    }
    C.b2p01 = pack2(__ldg(&b2[0]), __ldg(&b2[1]));
    C.b2p23 = pack2(__ldg(&b2[2]), __ldg(&b2[3]));
    C.w3p01 = pack2(__ldg(&W3[0]), __ldg(&W3[1]));
    C.w3p23 = pack2(__ldg(&W3[2]), __ldg(&W3[3]));
    C.b3p   = pack2(__ldg(&b3[0]), 0.0f);
    C.k02   = pack2(0.2f, 0.2f);

    __syncthreads();

    const int warp = tid >> 5;
    const int lane = tid & 31;

    // lane owns m = 4*lane .. 4*lane+3 ; negated V packed across m-pairs
    const float4 v0 = Vs[4 * lane + 0];
    const float4 v1 = Vs[4 * lane + 1];
    const float4 v2 = Vs[4 * lane + 2];
    const float4 v3 = Vs[4 * lane + 3];
    const u64 nvxA = pack2(-v0.x, -v1.x), nvyA = pack2(-v0.y, -v1.y), nvzA = pack2(-v0.z, -v1.z);
    const u64 nvxB = pack2(-v2.x, -v3.x), nvyB = pack2(-v2.y, -v3.y), nvzB = pack2(-v2.z, -v3.z);

    // layer-1 constants packed across hidden dim, per owned m
    const float4 cc0 = Cs[4 * lane + 0];
    const float4 cc1 = Cs[4 * lane + 1];
    const float4 cc2 = Cs[4 * lane + 2];
    const float4 cc3 = Cs[4 * lane + 3];
    const u64 c0_01 = pack2(cc0.x, cc0.y), c0_23 = pack2(cc0.z, cc0.w);
    const u64 c1_01 = pack2(cc1.x, cc1.y), c1_23 = pack2(cc1.z, cc1.w);
    const u64 c2_01 = pack2(cc2.x, cc2.y), c2_23 = pack2(cc2.z, cc2.w);
    const u64 c3_01 = pack2(cc3.x, cc3.y), c3_23 = pack2(cc3.z, cc3.w);

    const float* xb = xyz + (size_t)b * 3 * N_DIM;
    float* outb = out + (size_t)b * N_DIM * M_DIM;

    const int n_base = blockIdx.x * PTS_PER_CTA + warp * PTS_PER_WARP;

#pragma unroll
    for (int p = 0; p < PTS_PER_WARP; p++) {
        const int n = n_base + p;
        const float px = __ldg(&xb[n]);
        const float py = __ldg(&xb[N_DIM + n]);
        const float pz = __ldg(&xb[2 * N_DIM + n]);
        const u64 pxs = pack2(px, px), pys = pack2(py, py), pzs = pack2(pz, pz);

        // distances, packed across m-pairs
        u64 dxA = add2(pxs, nvxA), dyA = add2(pys, nvyA), dzA = add2(pzs, nvzA);
        u64 sA = fma2(dxA, dxA, fma2(dyA, dyA, mul2(dzA, dzA)));
        u64 dxB = add2(pxs, nvxB), dyB = add2(pys, nvyB), dzB = add2(pzs, nvzB);
        u64 sB = fma2(dxB, dxB, fma2(dyB, dyB, mul2(dzB, dzB)));
        float s0, s1, s2, s3;
        unpack2(sA, s0, s1); unpack2(sB, s2, s3);
        const float d0 = sqrt_approx(s0);
        const float d1 = sqrt_approx(s1);
        const float d2 = sqrt_approx(s2);
        const float d3 = sqrt_approx(s3);

        // warp-wide min/max over all 128 m (SHFL butterfly; redux.f32 needs sm_100a target)
        float mn = fminf(fminf(d0, d1), fminf(d2, d3));
        float mx = fmaxf(fmaxf(d0, d1), fmaxf(d2, d3));
#pragma unroll
        for (int off = 16; off > 0; off >>= 1) {
            mn = fminf(mn, __shfl_xor_sync(0xFFFFFFFFu, mn, off));
            mx = fmaxf(mx, __shfl_xor_sync(0xFFFFFFFFu, mx, off));
        }

        const float denom = mx - mn;
        const float inv = (denom > 0.0f) ? rcp_approx(denom) : 0.0f;
        const float nmninv = -mn * inv;

        float4 res;
        res.x = mlp_eval(fmaf(d0, inv, nmninv), c0_01, c0_23, C);
        res.y = mlp_eval(fmaf(d1, inv, nmninv), c1_01, c1_23, C);
        res.z = mlp_eval(fmaf(d2, inv, nmninv), c2_01, c2_23, C);
        res.w = mlp_eval(fmaf(d3, inv, nmninv), c3_01, c3_23, C);

        // coalesced: warp writes 128 contiguous floats
        reinterpret_cast<float4*>(outb + (size_t)n * M_DIM)[lane] = res;
    }
}

extern "C" void kernel_launch(void* const* d_in, const int* in_sizes, int n_in,
                              void* d_out, int out_size) {
    const float* xyz = (const float*)d_in[0];
    const float* V   = (const float*)d_in[1];
    const float* W1  = (const float*)d_in[2];
    const float* b1  = (const float*)d_in[3];
    const float* W2  = (const float*)d_in[4];
    const float* b2  = (const float*)d_in[5];
    const float* W3  = (const float*)d_in[6];
    const float* b3  = (const float*)d_in[7];
    float* out = (float*)d_out;

    dim3 grid(N_DIM / PTS_PER_CTA, B_DIM);  // (128, 8)
    featuration_kernel<<<grid, THREADS>>>(xyz, V, W1, b1, W2, b2, W3, b3, out);
}